// round 11
// baseline (speedup 1.0000x reference)
#include <cuda_runtime.h>
#include <cuda_bf16.h>
#include <math.h>
#include <stdint.h>

#define NN 32768
#define EE 524288
#define FF 32
#define HH 512
#define CC 10
#define GG 64

typedef __nv_bfloat16 bf16;

#define SCL 512.0f
#define ISCL (1.0f / 512.0f)

// ---------------- scratch ----------------------------------------------------
// A buffers: cols 0..511 = h split, cols 512..1023 = agg split (bf16 hi/lo planes)
// F planes: e4m3(lo*512) of h (cols 0..511 only), for cheap aggregation gathers.
__device__ __align__(128) bf16 g_A0hi[NN * 128], g_A0lo[NN * 128];
__device__ __align__(128) bf16 g_A1hi[NN * 1024], g_A1lo[NN * 1024];
__device__ __align__(128) bf16 g_A2hi[NN * 1024], g_A2lo[NN * 1024];
__device__ __align__(128) uint8_t g_F1[NN * 512], g_F2[NN * 512];
__device__ __align__(128) bf16 g_B0hi[HH * 128], g_B0lo[HH * 128];
__device__ __align__(128) bf16 g_Bhi[4 * HH * 1024], g_Blo[4 * HH * 1024];
__device__ int   g_rowptr[NN + 1];
__device__ int   g_cursor[NN];
__device__ int   g_cnt[NN];
__device__ int   g_colsrc[EE];
__device__ int   g_grow[GG + 1];
__device__ int   g_gcnt[GG];
__device__ float g_feat[GG * 2 * HH];
__device__ float g_m1[GG * HH];
__device__ float g_m2[GG * HH];

// ---------------- helpers ----------------------------------------------------
__device__ __forceinline__ uint32_t smem_u32(const void* p) {
    uint32_t r;
    asm("{ .reg .u64 t; cvta.to.shared.u64 t, %1; cvt.u32.u64 %0, t; }" : "=r"(r) : "l"(p));
    return r;
}
__device__ __forceinline__ void cpa16(uint32_t d, const void* s) {
    asm volatile("cp.async.cg.shared.global [%0], [%1], 16;" :: "r"(d), "l"(s));
}
#define CP_COMMIT() asm volatile("cp.async.commit_group;" ::: "memory")
__device__ __forceinline__ void ldsm4(uint32_t* r, uint32_t a) {
    asm volatile("ldmatrix.sync.aligned.m8n8.x4.shared.b16 {%0,%1,%2,%3}, [%4];"
                 : "=r"(r[0]), "=r"(r[1]), "=r"(r[2]), "=r"(r[3]) : "r"(a));
}
__device__ __forceinline__ void mma_bf16(float* c, const uint32_t* a, const uint32_t* b) {
    asm volatile("mma.sync.aligned.m16n8k16.row.col.f32.bf16.bf16.f32 "
                 "{%0,%1,%2,%3}, {%4,%5,%6,%7}, {%8,%9}, {%0,%1,%2,%3};"
                 : "+f"(c[0]), "+f"(c[1]), "+f"(c[2]), "+f"(c[3])
                 : "r"(a[0]), "r"(a[1]), "r"(a[2]), "r"(a[3]), "r"(b[0]), "r"(b[1]));
}
__device__ __forceinline__ void split_bf16(float v, bf16& hi, bf16& lo) {
    hi = __float2bfloat16_rn(v);
    lo = __float2bfloat16_rn(v - __bfloat162float(hi));
}
// pack two lo values (scaled by SCL) into e4m3x2: elem0 -> byte0, elem1 -> byte1
__device__ __forceinline__ uint16_t pkf8(float lo0, float lo1) {
    uint16_t r;
    asm("cvt.rn.satfinite.e4m3x2.f32 %0, %1, %2;" : "=h"(r)
        : "f"(lo1 * SCL), "f"(lo0 * SCL));
    return r;
}
// decode e4m3x2 -> float2 (byte0 -> .x)
__device__ __forceinline__ float2 def8(uint16_t p) {
    uint32_t h2;
    asm("cvt.rn.f16x2.e4m3x2 %0, %1;" : "=r"(h2) : "h"(p));
    __half2 hh = *(__half2*)&h2;
    return __half22float2(hh);
}
__device__ __forceinline__ uint32_t swz(uint32_t off) { return off ^ ((off >> 3) & 0x70); }

// ---------------- CSR build --------------------------------------------------
__global__ void k_zero_counts() {
    int i = blockIdx.x * blockDim.x + threadIdx.x;
    if (i < NN) g_cnt[i] = 0;
    if (i < GG) g_gcnt[i] = 0;
}
__global__ void k_hist(const int* __restrict__ ei, const int* __restrict__ batch) {
    int e = blockIdx.x * blockDim.x + threadIdx.x;
    if (e < EE) atomicAdd(&g_cnt[ei[EE + e]], 1);
    if (e < NN) atomicAdd(&g_gcnt[batch[e]], 1);
}
__global__ void k_scan() {
    __shared__ int sums[1024];
    const int per = NN / 1024;
    int tid = threadIdx.x, base = tid * per;
    int local[32];
    int s = 0;
    for (int i = 0; i < per; i++) { local[i] = s; s += g_cnt[base + i]; }
    sums[tid] = s;
    __syncthreads();
    for (int off = 1; off < 1024; off <<= 1) {
        int v = (tid >= off) ? sums[tid - off] : 0;
        __syncthreads();
        sums[tid] += v;
        __syncthreads();
    }
    int excl = (tid == 0) ? 0 : sums[tid - 1];
    for (int i = 0; i < per; i++) {
        int v = excl + local[i];
        g_rowptr[base + i] = v;
        g_cursor[base + i] = v;
    }
    if (tid == 1023) g_rowptr[NN] = sums[1023];
    if (tid == 0) {
        int t = 0;
        for (int g = 0; g < GG; g++) { g_grow[g] = t; t += g_gcnt[g]; }
        g_grow[GG] = t;
    }
}
__global__ void k_fill(const int* __restrict__ ei) {
    int e = blockIdx.x * blockDim.x + threadIdx.x;
    if (e >= EE) return;
    int p = atomicAdd(&g_cursor[ei[EE + e]], 1);
    g_colsrc[p] = ei[e];
}
__global__ void k_sortadj() {
    int v = blockIdx.x * blockDim.x + threadIdx.x;
    if (v >= NN) return;
    int s = g_rowptr[v], e = g_rowptr[v + 1];
    for (int i = s + 1; i < e; i++) {
        int key = g_colsrc[i];
        int j = i - 1;
        while (j >= s && g_colsrc[j] > key) { g_colsrc[j + 1] = g_colsrc[j]; j--; }
        g_colsrc[j + 1] = key;
    }
}

// ---------------- split prep -------------------------------------------------
__global__ void k_split_x(const float* __restrict__ x) {
    int i = blockIdx.x * blockDim.x + threadIdx.x;
    if (i >= NN * 64) return;
    int r = i >> 6, k = i & 63;
    float v = (k < FF) ? x[r * FF + k] : 0.f;
    bf16 hi, lo;
    split_bf16(v, hi, lo);
    g_A0hi[r * 128 + k] = hi;
    g_A0lo[r * 128 + k] = lo;
}
__global__ void k_split_w0(const float* __restrict__ wr, const float* __restrict__ ws) {
    int i = blockIdx.x * blockDim.x + threadIdx.x;
    if (i >= HH * 128) return;
    int n = i >> 7, k = i & 127;
    float v = 0.f;
    if (k < FF) v = wr[k * HH + n];
    else if (k >= 64 && k < 64 + FF) v = ws[(k - 64) * HH + n];
    bf16 hi, lo;
    split_bf16(v, hi, lo);
    g_B0hi[i] = hi;
    g_B0lo[i] = lo;
}
__global__ void k_split_w(const float* __restrict__ wr, const float* __restrict__ ws) {
    int i = blockIdx.x * blockDim.x + threadIdx.x;
    if (i >= 4 * HH * 1024) return;
    int l = i >> 19;
    int rem = i & ((1 << 19) - 1);
    int n = rem >> 10, k = rem & 1023;
    float v = (k < HH) ? wr[(size_t)l * HH * HH + (size_t)k * HH + n]
                       : ws[(size_t)l * HH * HH + (size_t)(k - HH) * HH + n];
    bf16 hi, lo;
    split_bf16(v, hi, lo);
    g_Bhi[i] = hi;
    g_Blo[i] = lo;
}

// ---------------- aggregation ------------------------------------------------
__global__ void k_agg32(const float* __restrict__ x) {
    int v = blockIdx.x * 4 + threadIdx.y;
    int lane = threadIdx.x;
    if (v >= NN) return;
    int s = g_rowptr[v], e = g_rowptr[v + 1];
    float acc0 = 0.f, acc1 = 0.f;
    int i = s;
    for (; i + 1 < e; i += 2) {
        acc0 += x[g_colsrc[i] * FF + lane];
        acc1 += x[g_colsrc[i + 1] * FF + lane];
    }
    if (i < e) acc0 += x[g_colsrc[i] * FF + lane];
    float acc = acc0 + acc1;
    bf16 hi, lo;
    split_bf16(acc, hi, lo);
    g_A0hi[v * 128 + 64 + lane] = hi;
    g_A0lo[v * 128 + 64 + lane] = lo;
    g_A0hi[v * 128 + 96 + lane] = __float2bfloat16(0.f);
    g_A0lo[v * 128 + 96 + lane] = __float2bfloat16(0.f);
}
// gather h as hi(bf16) + fp8(lo*512) -> exact-split agg into cols 512..1023
__global__ void k_agg512(const bf16* __restrict__ phi, const uint8_t* __restrict__ pf8,
                         bf16* __restrict__ ahi, bf16* __restrict__ alo) {
    int v = blockIdx.x, tx = threadIdx.x;
    int s = g_rowptr[v], e = g_rowptr[v + 1];
    float ah[4] = {0.f, 0.f, 0.f, 0.f};
    float af[4] = {0.f, 0.f, 0.f, 0.f};
    float bh2[4] = {0.f, 0.f, 0.f, 0.f};
    float bf2[4] = {0.f, 0.f, 0.f, 0.f};
    int i = s;
    for (; i + 1 < e; i += 2) {
        int u0 = g_colsrc[i], u1 = g_colsrc[i + 1];
        uint2 h0 = *(const uint2*)&phi[(size_t)u0 * 1024 + tx * 4];
        uint32_t f0 = *(const uint32_t*)&pf8[(size_t)u0 * 512 + tx * 4];
        uint2 h1 = *(const uint2*)&phi[(size_t)u1 * 1024 + tx * 4];
        uint32_t f1 = *(const uint32_t*)&pf8[(size_t)u1 * 512 + tx * 4];
        {
            float2 a = __bfloat1622float2(*(__nv_bfloat162*)&h0.x);
            float2 b = __bfloat1622float2(*(__nv_bfloat162*)&h0.y);
            float2 c = def8((uint16_t)(f0 & 0xffff));
            float2 d = def8((uint16_t)(f0 >> 16));
            ah[0] += a.x; ah[1] += a.y; ah[2] += b.x; ah[3] += b.y;
            af[0] += c.x; af[1] += c.y; af[2] += d.x; af[3] += d.y;
        }
        {
            float2 a = __bfloat1622float2(*(__nv_bfloat162*)&h1.x);
            float2 b = __bfloat1622float2(*(__nv_bfloat162*)&h1.y);
            float2 c = def8((uint16_t)(f1 & 0xffff));
            float2 d = def8((uint16_t)(f1 >> 16));
            bh2[0] += a.x; bh2[1] += a.y; bh2[2] += b.x; bh2[3] += b.y;
            bf2[0] += c.x; bf2[1] += c.y; bf2[2] += d.x; bf2[3] += d.y;
        }
    }
    if (i < e) {
        int u0 = g_colsrc[i];
        uint2 h0 = *(const uint2*)&phi[(size_t)u0 * 1024 + tx * 4];
        uint32_t f0 = *(const uint32_t*)&pf8[(size_t)u0 * 512 + tx * 4];
        float2 a = __bfloat1622float2(*(__nv_bfloat162*)&h0.x);
        float2 b = __bfloat1622float2(*(__nv_bfloat162*)&h0.y);
        float2 c = def8((uint16_t)(f0 & 0xffff));
        float2 d = def8((uint16_t)(f0 >> 16));
        ah[0] += a.x; ah[1] += a.y; ah[2] += b.x; ah[3] += b.y;
        af[0] += c.x; af[1] += c.y; af[2] += d.x; af[3] += d.y;
    }
    bf16 hi[4], lo[4];
#pragma unroll
    for (int j = 0; j < 4; j++) {
        float acc = (ah[j] + bh2[j]) + (af[j] + bf2[j]) * ISCL;
        split_bf16(acc, hi[j], lo[j]);
    }
    *(uint2*)&ahi[(size_t)v * 1024 + 512 + tx * 4] = *(uint2*)hi;
    *(uint2*)&alo[(size_t)v * 1024 + 512 + tx * 4] = *(uint2*)lo;
}

// ---------------- bf16 mma GEMM (mainloop identical to R4/R10) ----------------
#define STAGE_B 65536

__global__ __launch_bounds__(256, 1)
void k_mmagemm(const bf16* __restrict__ Ahi, const bf16* __restrict__ Alo,
               const bf16* __restrict__ Bhi, const bf16* __restrict__ Blo,
               const float* __restrict__ bias,
               bf16* __restrict__ ohi, bf16* __restrict__ olo,
               uint8_t* __restrict__ of8, int Kp) {
    extern __shared__ char smem[];
    uint32_t sb = smem_u32(smem);
    const int tid = threadIdx.x;
    const int wid = tid >> 5, lane = tid & 31;
    const int brow = blockIdx.y * 128;
    const int bcol = blockIdx.x * 128;
    const int wm = (wid & 1) * 64;
    const int wn = (wid >> 1) * 32;
    const int C = Kp >> 6;

    float acc[4][4][4];
#pragma unroll
    for (int i = 0; i < 4; i++)
#pragma unroll
        for (int j = 0; j < 4; j++)
#pragma unroll
            for (int q = 0; q < 4; q++) acc[i][j][q] = 0.f;

    auto copy_stage = [&](int buf, int c) {
        uint32_t st = sb + (uint32_t)buf * STAGE_B;
#pragma unroll
        for (int i = 0; i < 4; i++) {
            int id = tid * 4 + i;
            int r = id >> 3, u = id & 7;
            uint32_t sw = swz((uint32_t)(r * 128 + u * 16));
            const bf16* pa = Ahi + (size_t)(brow + r) * Kp + c * 64 + u * 8;
            const bf16* pl = Alo + (size_t)(brow + r) * Kp + c * 64 + u * 8;
            const bf16* pb = Bhi + (size_t)(bcol + r) * Kp + c * 64 + u * 8;
            const bf16* pc = Blo + (size_t)(bcol + r) * Kp + c * 64 + u * 8;
            cpa16(st + sw, pa);
            cpa16(st + 16384 + sw, pl);
            cpa16(st + 32768 + sw, pb);
            cpa16(st + 49152 + sw, pc);
        }
        CP_COMMIT();
    };

    const int a_row = wm + ((lane >> 3) & 1) * 8 + (lane & 7);
    const int a_ub  = lane >> 4;
    const int b_row = wn + ((lane >> 4) & 1) * 8 + (lane & 7);
    const int b_ub  = (lane >> 3) & 1;

    copy_stage(0, 0);

    for (int c = 0; c < C; c++) {
        int buf = c & 1;
        if (c + 1 < C) {
            copy_stage(buf ^ 1, c + 1);
            asm volatile("cp.async.wait_group 1;" ::: "memory");
        } else {
            asm volatile("cp.async.wait_group 0;" ::: "memory");
        }
        __syncthreads();

        uint32_t base = sb + (uint32_t)buf * STAGE_B;
#pragma unroll
        for (int ks = 0; ks < 4; ks++) {
            int ku = ks * 2;
            uint32_t ah[4][4], al[4][4], bh[2][4], bl[2][4];
#pragma unroll
            for (int i = 0; i < 4; i++) {
                uint32_t off = swz((uint32_t)((a_row + i * 16) * 128 + (ku + a_ub) * 16));
                ldsm4(ah[i], base + off);
                ldsm4(al[i], base + 16384 + off);
            }
#pragma unroll
            for (int j2 = 0; j2 < 2; j2++) {
                uint32_t off = swz((uint32_t)((b_row + j2 * 16) * 128 + (ku + b_ub) * 16));
                ldsm4(bh[j2], base + 32768 + off);
                ldsm4(bl[j2], base + 49152 + off);
            }
#pragma unroll
            for (int i = 0; i < 4; i++)
#pragma unroll
                for (int j = 0; j < 4; j++) {
                    const uint32_t* ph = &bh[j >> 1][(j & 1) * 2];
                    const uint32_t* pl2 = &bl[j >> 1][(j & 1) * 2];
                    mma_bf16(acc[i][j], ah[i], ph);
                    mma_bf16(acc[i][j], ah[i], pl2);
                    mma_bf16(acc[i][j], al[i], ph);
                }
        }
        __syncthreads();
    }

    // epilogue: bias + tanh -> hi, lo, fp8(lo*512) planes
#pragma unroll
    for (int i = 0; i < 4; i++) {
        int r0 = brow + wm + i * 16 + (lane >> 2);
#pragma unroll
        for (int j = 0; j < 4; j++) {
            int col = bcol + wn + j * 8 + (lane & 3) * 2;
            float b0v = bias[col], b1v = bias[col + 1];
            float v0 = tanhf(acc[i][j][0] + b0v);
            float v1 = tanhf(acc[i][j][1] + b1v);
            float v2 = tanhf(acc[i][j][2] + b0v);
            float v3 = tanhf(acc[i][j][3] + b1v);
            bf16 h0, l0, h1, l1;
            __nv_bfloat162 th, tl;
            split_bf16(v0, h0, l0); split_bf16(v1, h1, l1);
            th.x = h0; th.y = h1; tl.x = l0; tl.y = l1;
            *(__nv_bfloat162*)&ohi[(size_t)r0 * 1024 + col] = th;
            *(__nv_bfloat162*)&olo[(size_t)r0 * 1024 + col] = tl;
            *(uint16_t*)&of8[(size_t)r0 * 512 + col] =
                pkf8(__bfloat162float(l0), __bfloat162float(l1));
            split_bf16(v2, h0, l0); split_bf16(v3, h1, l1);
            th.x = h0; th.y = h1; tl.x = l0; tl.y = l1;
            *(__nv_bfloat162*)&ohi[(size_t)(r0 + 8) * 1024 + col] = th;
            *(__nv_bfloat162*)&olo[(size_t)(r0 + 8) * 1024 + col] = tl;
            *(uint16_t*)&of8[(size_t)(r0 + 8) * 512 + col] =
                pkf8(__bfloat162float(l0), __bfloat162float(l1));
        }
    }
}

// ---------------- pooling / MLP / head ---------------------------------------
__global__ void k_pool(const bf16* __restrict__ hhi, const bf16* __restrict__ hlo) {
    int g = blockIdx.x;
    int c = blockIdx.y * 128 + threadIdx.x;
    int s = g_grow[g], e = g_grow[g + 1];
    float mx = -INFINITY, sm = 0.f;
    for (int i = s; i < e; i++) {
        float v = __bfloat162float(hhi[(size_t)i * 1024 + c]) +
                  __bfloat162float(hlo[(size_t)i * 1024 + c]);
        mx = fmaxf(mx, v);
        sm += v;
    }
    g_feat[g * 2 * HH + c]      = mx;
    g_feat[g * 2 * HH + HH + c] = sm / fmaxf((float)(e - s), 1.f);
}
__global__ void k_mlp(const float* __restrict__ A, const float* __restrict__ W,
                      const float* __restrict__ b, float* __restrict__ out,
                      int K, int Nn) {
    int n = blockIdx.x * blockDim.x + threadIdx.x;
    int m = blockIdx.y;
    float s = b[n];
    for (int k = 0; k < K; k++) s += A[m * K + k] * W[k * Nn + n];
    out[m * Nn + n] = tanhf(s);
}
__global__ void k_head(const float* __restrict__ A, const float* __restrict__ W,
                       const float* __restrict__ b, float* __restrict__ out) {
    int g = blockIdx.x;
    int lane = threadIdx.x;
    float cls[CC];
#pragma unroll
    for (int c = 0; c < CC; c++) {
        float s = 0.f;
        for (int k = lane; k < HH; k += 32) s += A[g * HH + k] * W[k * CC + c];
#pragma unroll
        for (int off = 16; off; off >>= 1) s += __shfl_xor_sync(0xffffffffu, s, off);
        cls[c] = s + b[c];
    }
    float mx = -INFINITY;
#pragma unroll
    for (int c = 0; c < CC; c++) mx = fmaxf(mx, cls[c]);
    float se = 0.f;
#pragma unroll
    for (int c = 0; c < CC; c++) se += expf(cls[c] - mx);
    float lse = mx + logf(se);
    if (lane < CC) out[g * CC + lane] = cls[lane] - lse;
}

// ---------------- launcher ---------------------------------------------------
extern "C" void kernel_launch(void* const* d_in, const int* in_sizes, int n_in,
                              void* d_out, int out_size) {
    const float* x       = (const float*)d_in[0];
    const int*   ei      = (const int*)  d_in[1];
    const int*   batch   = (const int*)  d_in[2];
    const float* w_root0 = (const float*)d_in[3];
    const float* w_rel0  = (const float*)d_in[4];
    const float* b0      = (const float*)d_in[5];
    const float* w_root  = (const float*)d_in[6];
    const float* w_rel   = (const float*)d_in[7];
    const float* bb      = (const float*)d_in[8];
    const float* lin1_w  = (const float*)d_in[9];
    const float* lin1_b  = (const float*)d_in[10];
    const float* lin2_w  = (const float*)d_in[11];
    const float* lin2_b  = (const float*)d_in[12];
    const float* lin3_w  = (const float*)d_in[13];
    const float* lin3_b  = (const float*)d_in[14];
    float* out = (float*)d_out;

    float *feat, *m1, *m2;
    bf16 *a0h, *a0l, *a1h, *a1l, *a2h, *a2l, *b0h, *b0l, *bh, *bl;
    uint8_t *f1, *f2;
    cudaGetSymbolAddress((void**)&feat, g_feat);
    cudaGetSymbolAddress((void**)&m1, g_m1);
    cudaGetSymbolAddress((void**)&m2, g_m2);
    cudaGetSymbolAddress((void**)&a0h, g_A0hi);
    cudaGetSymbolAddress((void**)&a0l, g_A0lo);
    cudaGetSymbolAddress((void**)&a1h, g_A1hi);
    cudaGetSymbolAddress((void**)&a1l, g_A1lo);
    cudaGetSymbolAddress((void**)&a2h, g_A2hi);
    cudaGetSymbolAddress((void**)&a2l, g_A2lo);
    cudaGetSymbolAddress((void**)&f1, g_F1);
    cudaGetSymbolAddress((void**)&f2, g_F2);
    cudaGetSymbolAddress((void**)&b0h, g_B0hi);
    cudaGetSymbolAddress((void**)&b0l, g_B0lo);
    cudaGetSymbolAddress((void**)&bh, g_Bhi);
    cudaGetSymbolAddress((void**)&bl, g_Blo);

    cudaFuncSetAttribute(k_mmagemm, cudaFuncAttributeMaxDynamicSharedMemorySize,
                         2 * STAGE_B);
    const int dynsmem = 2 * STAGE_B;

    // CSR + graph segments
    k_zero_counts<<<(NN + 255) / 256, 256>>>();
    k_hist<<<(EE + 255) / 256, 256>>>(ei, batch);
    k_scan<<<1, 1024>>>();
    k_fill<<<(EE + 255) / 256, 256>>>(ei);
    k_sortadj<<<(NN + 127) / 128, 128>>>();

    // prep splits
    k_split_x<<<(NN * 64 + 255) / 256, 256>>>(x);
    k_split_w0<<<(HH * 128 + 255) / 256, 256>>>(w_root0, w_rel0);
    k_split_w<<<(4 * HH * 1024 + 255) / 256, 256>>>(w_root, w_rel);

    // layer 0: K'=128 -> writes buf1 cols 0..511 (+ fp8 plane f1)
    k_agg32<<<NN / 4, dim3(32, 4)>>>(x);
    k_mmagemm<<<dim3(HH / 128, NN / 128), 256, dynsmem>>>(
        a0h, a0l, b0h, b0l, b0, a1h, a1l, f1, 128);

    // layers 1..4: K'=1024, ping-pong buf1/buf2
    bf16 *chi = a1h, *clo = a1l, *nhi = a2h, *nlo = a2l;
    uint8_t *cf8 = f1, *nf8 = f2;
    for (int l = 0; l < 4; l++) {
        k_agg512<<<NN, 128>>>(chi, cf8, chi, clo);
        k_mmagemm<<<dim3(HH / 128, NN / 128), 256, dynsmem>>>(
            chi, clo, bh + (size_t)l * HH * 1024, bl + (size_t)l * HH * 1024,
            bb + l * HH, nhi, nlo, nf8, 1024);
        bf16* t1 = chi; chi = nhi; nhi = t1;
        bf16* t2 = clo; clo = nlo; nlo = t2;
        uint8_t* t3 = cf8; cf8 = nf8; nf8 = t3;
    }

    k_pool<<<dim3(GG, HH / 128), 128>>>(chi, clo);
    k_mlp<<<dim3(HH / 128, GG), 128>>>(feat, lin1_w, lin1_b, m1, 2 * HH, HH);
    k_mlp<<<dim3(HH / 128, GG), 128>>>(m1, lin2_w, lin2_b, m2, HH, HH);
    k_head<<<GG, 32>>>(m2, lin3_w, lin3_b, out);
}

// round 12
// speedup vs baseline: 1.3179x; 1.3179x over previous
#include <cuda_runtime.h>
#include <cuda_fp16.h>
#include <math.h>
#include <stdint.h>

#define NN 32768
#define EE 524288
#define FF 32
#define HH 512
#define CC 10
#define GG 64

typedef __half fp16;

// ---------------- scratch ----------------------------------------------------
// A planes (fp16 split ah/al): cols 0..511 = h, cols 512..1023 = agg
__device__ __align__(128) float g_hA[NN * HH];
__device__ __align__(128) float g_hB[NN * HH];
__device__ __align__(128) fp16 g_A0a[NN * 128], g_A0l[NN * 128];
__device__ __align__(128) fp16 g_A1a[NN * 1024], g_A1l[NN * 1024];
__device__ __align__(128) fp16 g_A2a[NN * 1024], g_A2l[NN * 1024];
__device__ __align__(128) fp16 g_B0[HH * 128];
__device__ __align__(128) fp16 g_Bw[4 * HH * 1024];
__device__ int   g_rowptr[NN + 1];
__device__ int   g_cursor[NN];
__device__ int   g_cnt[NN];
__device__ int   g_colsrc[EE];
__device__ int   g_grow[GG + 1];
__device__ int   g_gcnt[GG];
__device__ float g_feat[GG * 2 * HH];
__device__ float g_m1[GG * HH];
__device__ float g_m2[GG * HH];

// ---------------- helpers ----------------------------------------------------
__device__ __forceinline__ uint32_t smem_u32(const void* p) {
    uint32_t r;
    asm("{ .reg .u64 t; cvta.to.shared.u64 t, %1; cvt.u32.u64 %0, t; }" : "=r"(r) : "l"(p));
    return r;
}
__device__ __forceinline__ void cpa16(uint32_t d, const void* s) {
    asm volatile("cp.async.cg.shared.global [%0], [%1], 16;" :: "r"(d), "l"(s));
}
#define CP_COMMIT() asm volatile("cp.async.commit_group;" ::: "memory")
__device__ __forceinline__ void ldsm4(uint32_t* r, uint32_t a) {
    asm volatile("ldmatrix.sync.aligned.m8n8.x4.shared.b16 {%0,%1,%2,%3}, [%4];"
                 : "=r"(r[0]), "=r"(r[1]), "=r"(r[2]), "=r"(r[3]) : "r"(a));
}
__device__ __forceinline__ void mma_fp16(float* c, const uint32_t* a, const uint32_t* b) {
    asm volatile("mma.sync.aligned.m16n8k16.row.col.f32.f16.f16.f32 "
                 "{%0,%1,%2,%3}, {%4,%5,%6,%7}, {%8,%9}, {%0,%1,%2,%3};"
                 : "+f"(c[0]), "+f"(c[1]), "+f"(c[2]), "+f"(c[3])
                 : "r"(a[0]), "r"(a[1]), "r"(a[2]), "r"(a[3]), "r"(b[0]), "r"(b[1]));
}
__device__ __forceinline__ void split_fp16(float v, fp16& hi, fp16& lo) {
    hi = __float2half_rn(v);
    lo = __float2half_rn(v - __half2float(hi));
}
__device__ __forceinline__ uint32_t swz(uint32_t off) { return off ^ ((off >> 3) & 0x70); }

// ---------------- CSR build --------------------------------------------------
__global__ void k_zero_counts() {
    int i = blockIdx.x * blockDim.x + threadIdx.x;
    if (i < NN) g_cnt[i] = 0;
    if (i < GG) g_gcnt[i] = 0;
}
__global__ void k_hist(const int* __restrict__ ei, const int* __restrict__ batch) {
    int e = blockIdx.x * blockDim.x + threadIdx.x;
    if (e < EE) atomicAdd(&g_cnt[ei[EE + e]], 1);
    if (e < NN) atomicAdd(&g_gcnt[batch[e]], 1);
}
__global__ void k_scan() {
    __shared__ int sums[1024];
    const int per = NN / 1024;
    int tid = threadIdx.x, base = tid * per;
    int local[32];
    int s = 0;
    for (int i = 0; i < per; i++) { local[i] = s; s += g_cnt[base + i]; }
    sums[tid] = s;
    __syncthreads();
    for (int off = 1; off < 1024; off <<= 1) {
        int v = (tid >= off) ? sums[tid - off] : 0;
        __syncthreads();
        sums[tid] += v;
        __syncthreads();
    }
    int excl = (tid == 0) ? 0 : sums[tid - 1];
    for (int i = 0; i < per; i++) {
        int v = excl + local[i];
        g_rowptr[base + i] = v;
        g_cursor[base + i] = v;
    }
    if (tid == 1023) g_rowptr[NN] = sums[1023];
    if (tid == 0) {
        int t = 0;
        for (int g = 0; g < GG; g++) { g_grow[g] = t; t += g_gcnt[g]; }
        g_grow[GG] = t;
    }
}
__global__ void k_fill(const int* __restrict__ ei) {
    int e = blockIdx.x * blockDim.x + threadIdx.x;
    if (e >= EE) return;
    int p = atomicAdd(&g_cursor[ei[EE + e]], 1);
    g_colsrc[p] = ei[e];
}
__global__ void k_sortadj() {
    int v = blockIdx.x * blockDim.x + threadIdx.x;
    if (v >= NN) return;
    int s = g_rowptr[v], e = g_rowptr[v + 1];
    for (int i = s + 1; i < e; i++) {
        int key = g_colsrc[i];
        int j = i - 1;
        while (j >= s && g_colsrc[j] > key) { g_colsrc[j + 1] = g_colsrc[j]; j--; }
        g_colsrc[j + 1] = key;
    }
}

// ---------------- split prep -------------------------------------------------
__global__ void k_split_x(const float* __restrict__ x) {
    int i = blockIdx.x * blockDim.x + threadIdx.x;
    if (i >= NN * 64) return;
    int r = i >> 6, k = i & 63;
    float v = (k < FF) ? x[r * FF + k] : 0.f;
    fp16 hi, lo;
    split_fp16(v, hi, lo);
    g_A0a[r * 128 + k] = hi;
    g_A0l[r * 128 + k] = lo;
}
__global__ void k_split_w0(const float* __restrict__ wr, const float* __restrict__ ws) {
    int i = blockIdx.x * blockDim.x + threadIdx.x;
    if (i >= HH * 128) return;
    int n = i >> 7, k = i & 127;
    float v = 0.f;
    if (k < FF) v = wr[k * HH + n];
    else if (k >= 64 && k < 64 + FF) v = ws[(k - 64) * HH + n];
    g_B0[i] = __float2half_rn(v);
}
__global__ void k_split_w(const float* __restrict__ wr, const float* __restrict__ ws) {
    int i = blockIdx.x * blockDim.x + threadIdx.x;
    if (i >= 4 * HH * 1024) return;
    int l = i >> 19;
    int rem = i & ((1 << 19) - 1);
    int n = rem >> 10, k = rem & 1023;
    float v = (k < HH) ? wr[(size_t)l * HH * HH + (size_t)k * HH + n]
                       : ws[(size_t)l * HH * HH + (size_t)(k - HH) * HH + n];
    g_Bw[i] = __float2half_rn(v);
}

// ---------------- aggregation (fp32 gather, unroll x2) ------------------------
__global__ void k_agg32(const float* __restrict__ x) {
    int v = blockIdx.x * 4 + threadIdx.y;
    int lane = threadIdx.x;
    if (v >= NN) return;
    int s = g_rowptr[v], e = g_rowptr[v + 1];
    float acc0 = 0.f, acc1 = 0.f;
    int i = s;
    for (; i + 1 < e; i += 2) {
        acc0 += x[g_colsrc[i] * FF + lane];
        acc1 += x[g_colsrc[i + 1] * FF + lane];
    }
    if (i < e) acc0 += x[g_colsrc[i] * FF + lane];
    float acc = acc0 + acc1;
    fp16 hi, lo;
    split_fp16(acc, hi, lo);
    g_A0a[v * 128 + 64 + lane] = hi;
    g_A0l[v * 128 + 64 + lane] = lo;
    g_A0a[v * 128 + 96 + lane] = __float2half(0.f);
    g_A0l[v * 128 + 96 + lane] = __float2half(0.f);
}
__global__ void k_agg512(const float* __restrict__ src, fp16* __restrict__ aa,
                         fp16* __restrict__ al) {
    int v = blockIdx.x, tx = threadIdx.x;
    int s = g_rowptr[v], e = g_rowptr[v + 1];
    float4 a0 = make_float4(0.f, 0.f, 0.f, 0.f);
    float4 a1 = make_float4(0.f, 0.f, 0.f, 0.f);
    int i = s;
    for (; i + 1 < e; i += 2) {
        const float4 t0 = *(const float4*)&src[(size_t)g_colsrc[i] * HH + tx * 4];
        const float4 t1 = *(const float4*)&src[(size_t)g_colsrc[i + 1] * HH + tx * 4];
        a0.x += t0.x; a0.y += t0.y; a0.z += t0.z; a0.w += t0.w;
        a1.x += t1.x; a1.y += t1.y; a1.z += t1.z; a1.w += t1.w;
    }
    if (i < e) {
        const float4 t = *(const float4*)&src[(size_t)g_colsrc[i] * HH + tx * 4];
        a0.x += t.x; a0.y += t.y; a0.z += t.z; a0.w += t.w;
    }
    float a[4] = {a0.x + a1.x, a0.y + a1.y, a0.z + a1.z, a0.w + a1.w};
    fp16 hi[4], lo[4];
#pragma unroll
    for (int j = 0; j < 4; j++) split_fp16(a[j], hi[j], lo[j]);
    *(uint2*)&aa[(size_t)v * 1024 + 512 + tx * 4] = *(uint2*)hi;
    *(uint2*)&al[(size_t)v * 1024 + 512 + tx * 4] = *(uint2*)lo;
}

// ---------------- fp16 mma GEMM: 2 terms --------------------------------------
// CTA 128m x 128n, 8 warps (2x4), warp tile 64x32, BK=64, 2-stage, occ 1.
// D = (Aah + Aal) @ Bh;  out = tanh(D + bias).
// stage 48KB: Aah 16K | Aal 16K | Bh 16K.
#define STAGE_B 49152

__global__ __launch_bounds__(256, 1)
void k_mmagemm(const fp16* __restrict__ Aah, const fp16* __restrict__ Aal,
               const fp16* __restrict__ Bh,
               const float* __restrict__ bias, float* __restrict__ outf,
               fp16* __restrict__ oa, fp16* __restrict__ ol, int Kp) {
    extern __shared__ char smem[];
    uint32_t sb = smem_u32(smem);
    const int tid = threadIdx.x;
    const int wid = tid >> 5, lane = tid & 31;
    const int brow = blockIdx.y * 128;
    const int bcol = blockIdx.x * 128;
    const int wm = (wid & 1) * 64;
    const int wn = (wid >> 1) * 32;
    const int C = Kp >> 6;

    float acc[4][4][4];
#pragma unroll
    for (int i = 0; i < 4; i++)
#pragma unroll
        for (int j = 0; j < 4; j++)
#pragma unroll
            for (int q = 0; q < 4; q++) acc[i][j][q] = 0.f;

    auto copy_stage = [&](int buf, int c) {
        uint32_t st = sb + (uint32_t)buf * STAGE_B;
#pragma unroll
        for (int i = 0; i < 4; i++) {
            int id = tid * 4 + i;        // 0..1023
            int r = id >> 3, u = id & 7;
            uint32_t sw = swz((uint32_t)(r * 128 + u * 16));
            cpa16(st + sw, Aah + (size_t)(brow + r) * Kp + c * 64 + u * 8);
            cpa16(st + 16384 + sw, Aal + (size_t)(brow + r) * Kp + c * 64 + u * 8);
            cpa16(st + 32768 + sw, Bh + (size_t)(bcol + r) * Kp + c * 64 + u * 8);
        }
        CP_COMMIT();
    };

    const int a_row = wm + ((lane >> 3) & 1) * 8 + (lane & 7);
    const int a_ub  = lane >> 4;
    const int b_row = wn + ((lane >> 4) & 1) * 8 + (lane & 7);
    const int b_ub  = (lane >> 3) & 1;

    copy_stage(0, 0);

    for (int c = 0; c < C; c++) {
        int buf = c & 1;
        if (c + 1 < C) {
            copy_stage(buf ^ 1, c + 1);
            asm volatile("cp.async.wait_group 1;" ::: "memory");
        } else {
            asm volatile("cp.async.wait_group 0;" ::: "memory");
        }
        __syncthreads();

        uint32_t base = sb + (uint32_t)buf * STAGE_B;
#pragma unroll
        for (int ks = 0; ks < 4; ks++) {
            int ku = ks * 2;
            uint32_t ah[4][4], al[4][4], bh[2][4];
#pragma unroll
            for (int i = 0; i < 4; i++) {
                uint32_t off = swz((uint32_t)((a_row + i * 16) * 128 + (ku + a_ub) * 16));
                ldsm4(ah[i], base + off);
                ldsm4(al[i], base + 16384 + off);
            }
#pragma unroll
            for (int j2 = 0; j2 < 2; j2++) {
                uint32_t off = swz((uint32_t)((b_row + j2 * 16) * 128 + (ku + b_ub) * 16));
                ldsm4(bh[j2], base + 32768 + off);
            }
#pragma unroll
            for (int i = 0; i < 4; i++)
#pragma unroll
                for (int j = 0; j < 4; j++) {
                    const uint32_t* ph = &bh[j >> 1][(j & 1) * 2];
                    mma_fp16(acc[i][j], ah[i], ph);
                    mma_fp16(acc[i][j], al[i], ph);
                }
        }
        __syncthreads();
    }

    // epilogue: bias + tanh -> fp32 h + fp16 ah/al planes
#pragma unroll
    for (int i = 0; i < 4; i++) {
        int r0 = brow + wm + i * 16 + (lane >> 2);
#pragma unroll
        for (int j = 0; j < 4; j++) {
            int col = bcol + wn + j * 8 + (lane & 3) * 2;
            float b0v = bias[col], b1v = bias[col + 1];
            float v0 = tanhf(acc[i][j][0] + b0v);
            float v1 = tanhf(acc[i][j][1] + b1v);
            float v2 = tanhf(acc[i][j][2] + b0v);
            float v3 = tanhf(acc[i][j][3] + b1v);
            *(float2*)&outf[(size_t)r0 * HH + col] = make_float2(v0, v1);
            *(float2*)&outf[(size_t)(r0 + 8) * HH + col] = make_float2(v2, v3);
            fp16 h0, l0, h1, l1;
            __half2 th, tl;
            split_fp16(v0, h0, l0); split_fp16(v1, h1, l1);
            th = __halves2half2(h0, h1); tl = __halves2half2(l0, l1);
            *(__half2*)&oa[(size_t)r0 * 1024 + col] = th;
            *(__half2*)&ol[(size_t)r0 * 1024 + col] = tl;
            split_fp16(v2, h0, l0); split_fp16(v3, h1, l1);
            th = __halves2half2(h0, h1); tl = __halves2half2(l0, l1);
            *(__half2*)&oa[(size_t)(r0 + 8) * 1024 + col] = th;
            *(__half2*)&ol[(size_t)(r0 + 8) * 1024 + col] = tl;
        }
    }
}

// ---------------- pooling / MLP / head ---------------------------------------
__global__ void k_pool(const float* __restrict__ h) {
    int g = blockIdx.x;
    int c = blockIdx.y * 128 + threadIdx.x;
    int s = g_grow[g], e = g_grow[g + 1];
    float mx = -INFINITY, sm = 0.f;
    for (int i = s; i < e; i++) {
        float v = h[(size_t)i * HH + c];
        mx = fmaxf(mx, v);
        sm += v;
    }
    g_feat[g * 2 * HH + c]      = mx;
    g_feat[g * 2 * HH + HH + c] = sm / fmaxf((float)(e - s), 1.f);
}
__global__ void k_mlp(const float* __restrict__ A, const float* __restrict__ W,
                      const float* __restrict__ b, float* __restrict__ out,
                      int K, int Nn) {
    int n = blockIdx.x * blockDim.x + threadIdx.x;
    int m = blockIdx.y;
    float s = b[n];
    for (int k = 0; k < K; k++) s += A[m * K + k] * W[k * Nn + n];
    out[m * Nn + n] = tanhf(s);
}
__global__ void k_head(const float* __restrict__ A, const float* __restrict__ W,
                       const float* __restrict__ b, float* __restrict__ out) {
    int g = blockIdx.x;
    int lane = threadIdx.x;
    float cls[CC];
#pragma unroll
    for (int c = 0; c < CC; c++) {
        float s = 0.f;
        for (int k = lane; k < HH; k += 32) s += A[g * HH + k] * W[k * CC + c];
#pragma unroll
        for (int off = 16; off; off >>= 1) s += __shfl_xor_sync(0xffffffffu, s, off);
        cls[c] = s + b[c];
    }
    float mx = -INFINITY;
#pragma unroll
    for (int c = 0; c < CC; c++) mx = fmaxf(mx, cls[c]);
    float se = 0.f;
#pragma unroll
    for (int c = 0; c < CC; c++) se += expf(cls[c] - mx);
    float lse = mx + logf(se);
    if (lane < CC) out[g * CC + lane] = cls[lane] - lse;
}

// ---------------- launcher ---------------------------------------------------
extern "C" void kernel_launch(void* const* d_in, const int* in_sizes, int n_in,
                              void* d_out, int out_size) {
    const float* x       = (const float*)d_in[0];
    const int*   ei      = (const int*)  d_in[1];
    const int*   batch   = (const int*)  d_in[2];
    const float* w_root0 = (const float*)d_in[3];
    const float* w_rel0  = (const float*)d_in[4];
    const float* b0      = (const float*)d_in[5];
    const float* w_root  = (const float*)d_in[6];
    const float* w_rel   = (const float*)d_in[7];
    const float* bb      = (const float*)d_in[8];
    const float* lin1_w  = (const float*)d_in[9];
    const float* lin1_b  = (const float*)d_in[10];
    const float* lin2_w  = (const float*)d_in[11];
    const float* lin2_b  = (const float*)d_in[12];
    const float* lin3_w  = (const float*)d_in[13];
    const float* lin3_b  = (const float*)d_in[14];
    float* out = (float*)d_out;

    float *hA, *hB, *feat, *m1, *m2;
    fp16 *a0a, *a0l, *a1a, *a1l, *a2a, *a2l, *b0p, *bwp;
    cudaGetSymbolAddress((void**)&hA, g_hA);
    cudaGetSymbolAddress((void**)&hB, g_hB);
    cudaGetSymbolAddress((void**)&feat, g_feat);
    cudaGetSymbolAddress((void**)&m1, g_m1);
    cudaGetSymbolAddress((void**)&m2, g_m2);
    cudaGetSymbolAddress((void**)&a0a, g_A0a);
    cudaGetSymbolAddress((void**)&a0l, g_A0l);
    cudaGetSymbolAddress((void**)&a1a, g_A1a);
    cudaGetSymbolAddress((void**)&a1l, g_A1l);
    cudaGetSymbolAddress((void**)&a2a, g_A2a);
    cudaGetSymbolAddress((void**)&a2l, g_A2l);
    cudaGetSymbolAddress((void**)&b0p, g_B0);
    cudaGetSymbolAddress((void**)&bwp, g_Bw);

    cudaFuncSetAttribute(k_mmagemm, cudaFuncAttributeMaxDynamicSharedMemorySize,
                         2 * STAGE_B);
    const int dynsmem = 2 * STAGE_B;

    // CSR + graph segments
    k_zero_counts<<<(NN + 255) / 256, 256>>>();
    k_hist<<<(EE + 255) / 256, 256>>>(ei, batch);
    k_scan<<<1, 1024>>>();
    k_fill<<<(EE + 255) / 256, 256>>>(ei);
    k_sortadj<<<(NN + 127) / 128, 128>>>();

    // prep splits
    k_split_x<<<(NN * 64 + 255) / 256, 256>>>(x);
    k_split_w0<<<(HH * 128 + 255) / 256, 256>>>(w_root0, w_rel0);
    k_split_w<<<(4 * HH * 1024 + 255) / 256, 256>>>(w_root, w_rel);

    // layer 0: K'=128
    k_agg32<<<NN / 4, dim3(32, 4)>>>(x);
    k_mmagemm<<<dim3(HH / 128, NN / 128), 256, dynsmem>>>(
        a0a, a0l, b0p, b0, hA, a1a, a1l, 128);

    // layers 1..4: K'=1024
    float* hcur = hA;
    float* hnxt = hB;
    fp16 *aca = a1a, *acl = a1l, *ana = a2a, *anl = a2l;
    for (int l = 0; l < 4; l++) {
        k_agg512<<<NN, 128>>>(hcur, aca, acl);
        k_mmagemm<<<dim3(HH / 128, NN / 128), 256, dynsmem>>>(
            aca, acl, bwp + (size_t)l * HH * 1024,
            bb + l * HH, hnxt, ana, anl, 1024);
        float* tf = hcur; hcur = hnxt; hnxt = tf;
        fp16* t1 = aca; aca = ana; ana = t1;
        fp16* t2 = acl; acl = anl; anl = t2;
    }

    k_pool<<<dim3(GG, HH / 128), 128>>>(hcur);
    k_mlp<<<dim3(HH / 128, GG), 128>>>(feat, lin1_w, lin1_b, m1, 2 * HH, HH);
    k_mlp<<<dim3(HH / 128, GG), 128>>>(m1, lin2_w, lin2_b, m2, HH, HH);
    k_head<<<GG, 32>>>(m2, lin3_w, lin3_b, out);
}

// round 13
// speedup vs baseline: 1.3625x; 1.0339x over previous
#include <cuda_runtime.h>
#include <cuda_fp16.h>
#include <math.h>
#include <stdint.h>

#define NN 32768
#define EE 524288
#define FF 32
#define HH 512
#define CC 10
#define GG 64

typedef __half fp16;

// ---------------- scratch ----------------------------------------------------
// A planes (fp16 split ah/al): cols 0..511 = h, cols 512..1023 = agg
__device__ __align__(128) fp16 g_A0a[NN * 128], g_A0l[NN * 128];
__device__ __align__(128) fp16 g_A1a[NN * 1024], g_A1l[NN * 1024];
__device__ __align__(128) fp16 g_A2a[NN * 1024], g_A2l[NN * 1024];
__device__ __align__(128) fp16 g_B0[HH * 128];
__device__ __align__(128) fp16 g_Bw[4 * HH * 1024];
__device__ int   g_rowptr[NN + 1];
__device__ int   g_cursor[NN];
__device__ int   g_cnt[NN];
__device__ int   g_colsrc[EE];
__device__ int   g_grow[GG + 1];
__device__ int   g_gcnt[GG];
__device__ float g_feat[GG * 2 * HH];
__device__ float g_m1[GG * HH];
__device__ float g_m2[GG * HH];

// ---------------- helpers ----------------------------------------------------
__device__ __forceinline__ uint32_t smem_u32(const void* p) {
    uint32_t r;
    asm("{ .reg .u64 t; cvta.to.shared.u64 t, %1; cvt.u32.u64 %0, t; }" : "=r"(r) : "l"(p));
    return r;
}
__device__ __forceinline__ void cpa16(uint32_t d, const void* s) {
    asm volatile("cp.async.cg.shared.global [%0], [%1], 16;" :: "r"(d), "l"(s));
}
#define CP_COMMIT() asm volatile("cp.async.commit_group;" ::: "memory")
__device__ __forceinline__ void ldsm4(uint32_t* r, uint32_t a) {
    asm volatile("ldmatrix.sync.aligned.m8n8.x4.shared.b16 {%0,%1,%2,%3}, [%4];"
                 : "=r"(r[0]), "=r"(r[1]), "=r"(r[2]), "=r"(r[3]) : "r"(a));
}
__device__ __forceinline__ void mma_fp16(float* c, const uint32_t* a, const uint32_t* b) {
    asm volatile("mma.sync.aligned.m16n8k16.row.col.f32.f16.f16.f32 "
                 "{%0,%1,%2,%3}, {%4,%5,%6,%7}, {%8,%9}, {%0,%1,%2,%3};"
                 : "+f"(c[0]), "+f"(c[1]), "+f"(c[2]), "+f"(c[3])
                 : "r"(a[0]), "r"(a[1]), "r"(a[2]), "r"(a[3]), "r"(b[0]), "r"(b[1]));
}
__device__ __forceinline__ void split_fp16(float v, fp16& hi, fp16& lo) {
    hi = __float2half_rn(v);
    lo = __float2half_rn(v - __half2float(hi));
}
__device__ __forceinline__ uint32_t swz(uint32_t off) { return off ^ ((off >> 3) & 0x70); }

// ---------------- CSR build --------------------------------------------------
__global__ void k_zero_counts() {
    int i = blockIdx.x * blockDim.x + threadIdx.x;
    if (i < NN) g_cnt[i] = 0;
    if (i < GG) g_gcnt[i] = 0;
}
__global__ void k_hist(const int* __restrict__ ei, const int* __restrict__ batch) {
    int e = blockIdx.x * blockDim.x + threadIdx.x;
    if (e < EE) atomicAdd(&g_cnt[ei[EE + e]], 1);
    if (e < NN) atomicAdd(&g_gcnt[batch[e]], 1);
}
__global__ void k_scan() {
    __shared__ int sums[1024];
    const int per = NN / 1024;
    int tid = threadIdx.x, base = tid * per;
    int local[32];
    int s = 0;
    for (int i = 0; i < per; i++) { local[i] = s; s += g_cnt[base + i]; }
    sums[tid] = s;
    __syncthreads();
    for (int off = 1; off < 1024; off <<= 1) {
        int v = (tid >= off) ? sums[tid - off] : 0;
        __syncthreads();
        sums[tid] += v;
        __syncthreads();
    }
    int excl = (tid == 0) ? 0 : sums[tid - 1];
    for (int i = 0; i < per; i++) {
        int v = excl + local[i];
        g_rowptr[base + i] = v;
        g_cursor[base + i] = v;
    }
    if (tid == 1023) g_rowptr[NN] = sums[1023];
    if (tid == 0) {
        int t = 0;
        for (int g = 0; g < GG; g++) { g_grow[g] = t; t += g_gcnt[g]; }
        g_grow[GG] = t;
    }
}
__global__ void k_fill(const int* __restrict__ ei) {
    int e = blockIdx.x * blockDim.x + threadIdx.x;
    if (e >= EE) return;
    int p = atomicAdd(&g_cursor[ei[EE + e]], 1);
    g_colsrc[p] = ei[e];
}
__global__ void k_sortadj() {
    int v = blockIdx.x * blockDim.x + threadIdx.x;
    if (v >= NN) return;
    int s = g_rowptr[v], e = g_rowptr[v + 1];
    for (int i = s + 1; i < e; i++) {
        int key = g_colsrc[i];
        int j = i - 1;
        while (j >= s && g_colsrc[j] > key) { g_colsrc[j + 1] = g_colsrc[j]; j--; }
        g_colsrc[j + 1] = key;
    }
}

// ---------------- split prep -------------------------------------------------
__global__ void k_split_x(const float* __restrict__ x) {
    int i = blockIdx.x * blockDim.x + threadIdx.x;
    if (i >= NN * 64) return;
    int r = i >> 6, k = i & 63;
    float v = (k < FF) ? x[r * FF + k] : 0.f;
    fp16 hi, lo;
    split_fp16(v, hi, lo);
    g_A0a[r * 128 + k] = hi;
    g_A0l[r * 128 + k] = lo;
}
__global__ void k_split_w0(const float* __restrict__ wr, const float* __restrict__ ws) {
    int i = blockIdx.x * blockDim.x + threadIdx.x;
    if (i >= HH * 128) return;
    int n = i >> 7, k = i & 127;
    float v = 0.f;
    if (k < FF) v = wr[k * HH + n];
    else if (k >= 64 && k < 64 + FF) v = ws[(k - 64) * HH + n];
    g_B0[i] = __float2half_rn(v);
}
__global__ void k_split_w(const float* __restrict__ wr, const float* __restrict__ ws) {
    int i = blockIdx.x * blockDim.x + threadIdx.x;
    if (i >= 4 * HH * 1024) return;
    int l = i >> 19;
    int rem = i & ((1 << 19) - 1);
    int n = rem >> 10, k = rem & 1023;
    float v = (k < HH) ? wr[(size_t)l * HH * HH + (size_t)k * HH + n]
                       : ws[(size_t)l * HH * HH + (size_t)(k - HH) * HH + n];
    g_Bw[i] = __float2half_rn(v);
}

// ---------------- aggregation ------------------------------------------------
__global__ void k_agg32(const float* __restrict__ x) {
    int v = blockIdx.x * 4 + threadIdx.y;
    int lane = threadIdx.x;
    if (v >= NN) return;
    int s = g_rowptr[v], e = g_rowptr[v + 1];
    float acc0 = 0.f, acc1 = 0.f;
    int i = s;
    for (; i + 1 < e; i += 2) {
        acc0 += x[g_colsrc[i] * FF + lane];
        acc1 += x[g_colsrc[i + 1] * FF + lane];
    }
    if (i < e) acc0 += x[g_colsrc[i] * FF + lane];
    float acc = acc0 + acc1;
    fp16 hi, lo;
    split_fp16(acc, hi, lo);
    g_A0a[v * 128 + 64 + lane] = hi;
    g_A0l[v * 128 + 64 + lane] = lo;
    g_A0a[v * 128 + 96 + lane] = __float2half(0.f);
    g_A0l[v * 128 + 96 + lane] = __float2half(0.f);
}
// gather only the fp16 hi-plane of h (cols 0..511) -> split agg into cols 512..1023
__global__ void k_agg512(fp16* __restrict__ aa, fp16* __restrict__ al) {
    int v = blockIdx.x, tx = threadIdx.x;
    int s = g_rowptr[v], e = g_rowptr[v + 1];
    float p0[4] = {0.f, 0.f, 0.f, 0.f};
    float p1[4] = {0.f, 0.f, 0.f, 0.f};
    int i = s;
    for (; i + 1 < e; i += 2) {
        uint2 t0 = *(const uint2*)&aa[(size_t)g_colsrc[i] * 1024 + tx * 4];
        uint2 t1 = *(const uint2*)&aa[(size_t)g_colsrc[i + 1] * 1024 + tx * 4];
        float2 a = __half22float2(*(__half2*)&t0.x);
        float2 b = __half22float2(*(__half2*)&t0.y);
        float2 c = __half22float2(*(__half2*)&t1.x);
        float2 d = __half22float2(*(__half2*)&t1.y);
        p0[0] += a.x; p0[1] += a.y; p0[2] += b.x; p0[3] += b.y;
        p1[0] += c.x; p1[1] += c.y; p1[2] += d.x; p1[3] += d.y;
    }
    if (i < e) {
        uint2 t0 = *(const uint2*)&aa[(size_t)g_colsrc[i] * 1024 + tx * 4];
        float2 a = __half22float2(*(__half2*)&t0.x);
        float2 b = __half22float2(*(__half2*)&t0.y);
        p0[0] += a.x; p0[1] += a.y; p0[2] += b.x; p0[3] += b.y;
    }
    fp16 hi[4], lo[4];
#pragma unroll
    for (int j = 0; j < 4; j++) split_fp16(p0[j] + p1[j], hi[j], lo[j]);
    *(uint2*)&aa[(size_t)v * 1024 + 512 + tx * 4] = *(uint2*)hi;
    *(uint2*)&al[(size_t)v * 1024 + 512 + tx * 4] = *(uint2*)lo;
}

// ---------------- fp16 mma GEMM: 2 terms (mainloop frozen) --------------------
// CTA 128m x 128n, 8 warps (2x4), warp tile 64x32, BK=64, 2-stage, occ 1.
// D = (Aah + Aal) @ Bh;  out = tanh(D + bias) -> fp16 ah/al planes only.
#define STAGE_B 49152

__global__ __launch_bounds__(256, 1)
void k_mmagemm(const fp16* __restrict__ Aah, const fp16* __restrict__ Aal,
               const fp16* __restrict__ Bh,
               const float* __restrict__ bias,
               fp16* __restrict__ oa, fp16* __restrict__ ol, int Kp) {
    extern __shared__ char smem[];
    uint32_t sb = smem_u32(smem);
    const int tid = threadIdx.x;
    const int wid = tid >> 5, lane = tid & 31;
    const int brow = blockIdx.y * 128;
    const int bcol = blockIdx.x * 128;
    const int wm = (wid & 1) * 64;
    const int wn = (wid >> 1) * 32;
    const int C = Kp >> 6;

    float acc[4][4][4];
#pragma unroll
    for (int i = 0; i < 4; i++)
#pragma unroll
        for (int j = 0; j < 4; j++)
#pragma unroll
            for (int q = 0; q < 4; q++) acc[i][j][q] = 0.f;

    auto copy_stage = [&](int buf, int c) {
        uint32_t st = sb + (uint32_t)buf * STAGE_B;
#pragma unroll
        for (int i = 0; i < 4; i++) {
            int id = tid * 4 + i;
            int r = id >> 3, u = id & 7;
            uint32_t sw = swz((uint32_t)(r * 128 + u * 16));
            cpa16(st + sw, Aah + (size_t)(brow + r) * Kp + c * 64 + u * 8);
            cpa16(st + 16384 + sw, Aal + (size_t)(brow + r) * Kp + c * 64 + u * 8);
            cpa16(st + 32768 + sw, Bh + (size_t)(bcol + r) * Kp + c * 64 + u * 8);
        }
        CP_COMMIT();
    };

    const int a_row = wm + ((lane >> 3) & 1) * 8 + (lane & 7);
    const int a_ub  = lane >> 4;
    const int b_row = wn + ((lane >> 4) & 1) * 8 + (lane & 7);
    const int b_ub  = (lane >> 3) & 1;

    copy_stage(0, 0);

    for (int c = 0; c < C; c++) {
        int buf = c & 1;
        if (c + 1 < C) {
            copy_stage(buf ^ 1, c + 1);
            asm volatile("cp.async.wait_group 1;" ::: "memory");
        } else {
            asm volatile("cp.async.wait_group 0;" ::: "memory");
        }
        __syncthreads();

        uint32_t base = sb + (uint32_t)buf * STAGE_B;
#pragma unroll
        for (int ks = 0; ks < 4; ks++) {
            int ku = ks * 2;
            uint32_t ah[4][4], al[4][4], bh[2][4];
#pragma unroll
            for (int i = 0; i < 4; i++) {
                uint32_t off = swz((uint32_t)((a_row + i * 16) * 128 + (ku + a_ub) * 16));
                ldsm4(ah[i], base + off);
                ldsm4(al[i], base + 16384 + off);
            }
#pragma unroll
            for (int j2 = 0; j2 < 2; j2++) {
                uint32_t off = swz((uint32_t)((b_row + j2 * 16) * 128 + (ku + b_ub) * 16));
                ldsm4(bh[j2], base + 32768 + off);
            }
#pragma unroll
            for (int i = 0; i < 4; i++)
#pragma unroll
                for (int j = 0; j < 4; j++) {
                    const uint32_t* ph = &bh[j >> 1][(j & 1) * 2];
                    mma_fp16(acc[i][j], ah[i], ph);
                    mma_fp16(acc[i][j], al[i], ph);
                }
        }
        __syncthreads();
    }

    // epilogue: bias + tanh -> fp16 ah/al planes
#pragma unroll
    for (int i = 0; i < 4; i++) {
        int r0 = brow + wm + i * 16 + (lane >> 2);
#pragma unroll
        for (int j = 0; j < 4; j++) {
            int col = bcol + wn + j * 8 + (lane & 3) * 2;
            float b0v = bias[col], b1v = bias[col + 1];
            float v0 = tanhf(acc[i][j][0] + b0v);
            float v1 = tanhf(acc[i][j][1] + b1v);
            float v2 = tanhf(acc[i][j][2] + b0v);
            float v3 = tanhf(acc[i][j][3] + b1v);
            fp16 h0, l0, h1, l1;
            __half2 th, tl;
            split_fp16(v0, h0, l0); split_fp16(v1, h1, l1);
            th = __halves2half2(h0, h1); tl = __halves2half2(l0, l1);
            *(__half2*)&oa[(size_t)r0 * 1024 + col] = th;
            *(__half2*)&ol[(size_t)r0 * 1024 + col] = tl;
            split_fp16(v2, h0, l0); split_fp16(v3, h1, l1);
            th = __halves2half2(h0, h1); tl = __halves2half2(l0, l1);
            *(__half2*)&oa[(size_t)(r0 + 8) * 1024 + col] = th;
            *(__half2*)&ol[(size_t)(r0 + 8) * 1024 + col] = tl;
        }
    }
}

// ---------------- pooling / MLP / head ---------------------------------------
__global__ void k_pool(const fp16* __restrict__ ha, const fp16* __restrict__ hl) {
    int g = blockIdx.x;
    int c = blockIdx.y * 128 + threadIdx.x;
    int s = g_grow[g], e = g_grow[g + 1];
    float mx = -INFINITY, sm = 0.f;
    for (int i = s; i < e; i++) {
        float v = __half2float(ha[(size_t)i * 1024 + c]) +
                  __half2float(hl[(size_t)i * 1024 + c]);
        mx = fmaxf(mx, v);
        sm += v;
    }
    g_feat[g * 2 * HH + c]      = mx;
    g_feat[g * 2 * HH + HH + c] = sm / fmaxf((float)(e - s), 1.f);
}
__global__ void k_mlp(const float* __restrict__ A, const float* __restrict__ W,
                      const float* __restrict__ b, float* __restrict__ out,
                      int K, int Nn) {
    int n = blockIdx.x * blockDim.x + threadIdx.x;
    int m = blockIdx.y;
    float s = b[n];
    for (int k = 0; k < K; k++) s += A[m * K + k] * W[k * Nn + n];
    out[m * Nn + n] = tanhf(s);
}
__global__ void k_head(const float* __restrict__ A, const float* __restrict__ W,
                       const float* __restrict__ b, float* __restrict__ out) {
    int g = blockIdx.x;
    int lane = threadIdx.x;
    float cls[CC];
#pragma unroll
    for (int c = 0; c < CC; c++) {
        float s = 0.f;
        for (int k = lane; k < HH; k += 32) s += A[g * HH + k] * W[k * CC + c];
#pragma unroll
        for (int off = 16; off; off >>= 1) s += __shfl_xor_sync(0xffffffffu, s, off);
        cls[c] = s + b[c];
    }
    float mx = -INFINITY;
#pragma unroll
    for (int c = 0; c < CC; c++) mx = fmaxf(mx, cls[c]);
    float se = 0.f;
#pragma unroll
    for (int c = 0; c < CC; c++) se += expf(cls[c] - mx);
    float lse = mx + logf(se);
    if (lane < CC) out[g * CC + lane] = cls[lane] - lse;
}

// ---------------- launcher ---------------------------------------------------
extern "C" void kernel_launch(void* const* d_in, const int* in_sizes, int n_in,
                              void* d_out, int out_size) {
    const float* x       = (const float*)d_in[0];
    const int*   ei      = (const int*)  d_in[1];
    const int*   batch   = (const int*)  d_in[2];
    const float* w_root0 = (const float*)d_in[3];
    const float* w_rel0  = (const float*)d_in[4];
    const float* b0      = (const float*)d_in[5];
    const float* w_root  = (const float*)d_in[6];
    const float* w_rel   = (const float*)d_in[7];
    const float* bb      = (const float*)d_in[8];
    const float* lin1_w  = (const float*)d_in[9];
    const float* lin1_b  = (const float*)d_in[10];
    const float* lin2_w  = (const float*)d_in[11];
    const float* lin2_b  = (const float*)d_in[12];
    const float* lin3_w  = (const float*)d_in[13];
    const float* lin3_b  = (const float*)d_in[14];
    float* out = (float*)d_out;

    float *feat, *m1, *m2;
    fp16 *a0a, *a0l, *a1a, *a1l, *a2a, *a2l, *b0p, *bwp;
    cudaGetSymbolAddress((void**)&feat, g_feat);
    cudaGetSymbolAddress((void**)&m1, g_m1);
    cudaGetSymbolAddress((void**)&m2, g_m2);
    cudaGetSymbolAddress((void**)&a0a, g_A0a);
    cudaGetSymbolAddress((void**)&a0l, g_A0l);
    cudaGetSymbolAddress((void**)&a1a, g_A1a);
    cudaGetSymbolAddress((void**)&a1l, g_A1l);
    cudaGetSymbolAddress((void**)&a2a, g_A2a);
    cudaGetSymbolAddress((void**)&a2l, g_A2l);
    cudaGetSymbolAddress((void**)&b0p, g_B0);
    cudaGetSymbolAddress((void**)&bwp, g_Bw);

    cudaFuncSetAttribute(k_mmagemm, cudaFuncAttributeMaxDynamicSharedMemorySize,
                         2 * STAGE_B);
    const int dynsmem = 2 * STAGE_B;

    // CSR + graph segments
    k_zero_counts<<<(NN + 255) / 256, 256>>>();
    k_hist<<<(EE + 255) / 256, 256>>>(ei, batch);
    k_scan<<<1, 1024>>>();
    k_fill<<<(EE + 255) / 256, 256>>>(ei);
    k_sortadj<<<(NN + 127) / 128, 128>>>();

    // prep splits
    k_split_x<<<(NN * 64 + 255) / 256, 256>>>(x);
    k_split_w0<<<(HH * 128 + 255) / 256, 256>>>(w_root0, w_rel0);
    k_split_w<<<(4 * HH * 1024 + 255) / 256, 256>>>(w_root, w_rel);

    // layer 0: K'=128 -> writes buf1 cols 0..511
    k_agg32<<<NN / 4, dim3(32, 4)>>>(x);
    k_mmagemm<<<dim3(HH / 128, NN / 128), 256, dynsmem>>>(
        a0a, a0l, b0p, b0, a1a, a1l, 128);

    // layers 1..4: K'=1024, ping-pong buf1/buf2
    fp16 *aca = a1a, *acl = a1l, *ana = a2a, *anl = a2l;
    for (int l = 0; l < 4; l++) {
        k_agg512<<<NN, 128>>>(aca, acl);
        k_mmagemm<<<dim3(HH / 128, NN / 128), 256, dynsmem>>>(
            aca, acl, bwp + (size_t)l * HH * 1024,
            bb + l * HH, ana, anl, 1024);
        fp16* t1 = aca; aca = ana; ana = t1;
        fp16* t2 = acl; acl = anl; anl = t2;
    }

    k_pool<<<dim3(GG, HH / 128), 128>>>(aca, acl);
    k_mlp<<<dim3(HH / 128, GG), 128>>>(feat, lin1_w, lin1_b, m1, 2 * HH, HH);
    k_mlp<<<dim3(HH / 128, GG), 128>>>(m1, lin2_w, lin2_b, m2, HH, HH);
    k_head<<<GG, 32>>>(m2, lin3_w, lin3_b, out);
}